// round 1
// baseline (speedup 1.0000x reference)
#include <cuda_runtime.h>
#include <math_constants.h>

#define DIMD 256
#define NTOK 4096
#define BATCH 4
#define ROWS_TOTAL (BATCH * NTOK)
#define ATT_SCALE 0.17677669529663687f
#define THRESH 0.6f
#define PITCH 132

typedef unsigned long long ull;

// ---------------- scratch (device globals; no allocation allowed) -------------
__device__ float g_q[ROWS_TOTAL * DIMD];
__device__ float g_k[ROWS_TOTAL * DIMD];
__device__ float g_z[ROWS_TOTAL * DIMD];
__device__ float g_M[DIMD * DIMD];
__device__ float g_p[ROWS_TOTAL];
__device__ int   g_j[ROWS_TOTAL];

// ---------------- f32x2 helpers ----------------------------------------------
__device__ __forceinline__ ull pack_dup(float x) {
    ull d;
    asm("mov.b64 %0, {%1, %1};" : "=l"(d) : "r"(__float_as_uint(x)));
    return d;
}
__device__ __forceinline__ void fma2(ull &d, ull a, ull b) {
    asm("fma.rn.f32x2 %0, %1, %2, %0;" : "+l"(d) : "l"(a), "l"(b));
}
__device__ __forceinline__ float2 unpack2(ull v) {
    unsigned lo, hi;
    asm("mov.b64 {%0, %1}, %2;" : "=r"(lo), "=r"(hi) : "l"(v));
    return make_float2(__uint_as_float(lo), __uint_as_float(hi));
}

// Load 128 rows x 32 k-cols chunk (row stride DIMD) TRANSPOSED into dst[32][PITCH]
// src must already point at (row_base*DIMD + kk).
__device__ __forceinline__ void load_tile_T(float (*dst)[PITCH], const float* __restrict__ src, int tid) {
#pragma unroll
    for (int l = 0; l < 4; l++) {
        int idx = tid + l * 256;
        int row = idx >> 3;
        int k4  = idx & 7;
        float4 v = *(const float4*)(src + row * DIMD + k4 * 4);
        dst[k4 * 4 + 0][row] = v.x;
        dst[k4 * 4 + 1][row] = v.y;
        dst[k4 * 4 + 2][row] = v.z;
        dst[k4 * 4 + 3][row] = v.w;
    }
}

// Load 32 k-rows x 128 cols chunk (row stride DIMD) NATURAL into dst[32][PITCH]
__device__ __forceinline__ void load_tile_N(float (*dst)[PITCH], const float* __restrict__ src, int tid) {
#pragma unroll
    for (int l = 0; l < 4; l++) {
        int idx = tid + l * 256;
        int k  = idx >> 5;
        int c4 = idx & 31;
        float4 v = *(const float4*)(src + k * DIMD + c4 * 4);
        *(float4*)&dst[k][c4 * 4] = v;   // row base = 528*k bytes, 16B aligned
    }
}

// one K-step of the 128x128 (8x8 per-thread) f32x2 micro-kernel
__device__ __forceinline__ void mma_step(const float (*as_)[PITCH], const float (*bs_)[PITCH],
                                         int k, int tx, int ty, ull acc[8][4]) {
    ull b[4];
    const ull* bp_ = (const ull*)&bs_[k][tx * 8];
#pragma unroll
    for (int c = 0; c < 4; c++) b[c] = bp_[c];

    const float2* ap_ = (const float2*)&as_[k][ty * 8];
    float2 a01 = ap_[0], a23 = ap_[1], a45 = ap_[2], a67 = ap_[3];
    ull A[8];
    A[0] = pack_dup(a01.x); A[1] = pack_dup(a01.y);
    A[2] = pack_dup(a23.x); A[3] = pack_dup(a23.y);
    A[4] = pack_dup(a45.x); A[5] = pack_dup(a45.y);
    A[6] = pack_dup(a67.x); A[7] = pack_dup(a67.y);
#pragma unroll
    for (int r = 0; r < 8; r++)
#pragma unroll
        for (int c = 0; c < 4; c++)
            fma2(acc[r][c], A[r], b[c]);
}

// ---------------- generic tiled GEMM: C[M x 256] = A[M x 256] @ B[256 x 256] (+bias)
__global__ __launch_bounds__(256) void gemm_kernel(const float* __restrict__ A,
                                                   const float* __restrict__ B,
                                                   float* __restrict__ C,
                                                   const float* __restrict__ bias,
                                                   int hasBias) {
    __shared__ float as_[32][PITCH];
    __shared__ float bs_[32][PITCH];
    int tid = threadIdx.x, tx = tid & 15, ty = tid >> 4;
    int rb = blockIdx.x * 128, cb = blockIdx.y * 128;

    ull acc[8][4];
#pragma unroll
    for (int r = 0; r < 8; r++)
#pragma unroll
        for (int c = 0; c < 4; c++) acc[r][c] = 0ULL;

    for (int kk = 0; kk < DIMD; kk += 32) {
        load_tile_T(as_, A + (size_t)rb * DIMD + kk, tid);
        load_tile_N(bs_, B + (size_t)kk * DIMD + cb, tid);
        __syncthreads();
#pragma unroll 8
        for (int k = 0; k < 32; k++) mma_step(as_, bs_, k, tx, ty, acc);
        __syncthreads();
    }

    float bv[8];
    if (hasBias) {
        float4 b0 = *(const float4*)(bias + cb + tx * 8);
        float4 b1 = *(const float4*)(bias + cb + tx * 8 + 4);
        bv[0] = b0.x; bv[1] = b0.y; bv[2] = b0.z; bv[3] = b0.w;
        bv[4] = b1.x; bv[5] = b1.y; bv[6] = b1.z; bv[7] = b1.w;
    } else {
#pragma unroll
        for (int i = 0; i < 8; i++) bv[i] = 0.f;
    }

#pragma unroll
    for (int r = 0; r < 8; r++) {
        float v[8];
#pragma unroll
        for (int c = 0; c < 4; c++) {
            float2 u = unpack2(acc[r][c]);
            v[2 * c]     = u.x + bv[2 * c];
            v[2 * c + 1] = u.y + bv[2 * c + 1];
        }
        int row = rb + ty * 8 + r;
        float* dst = C + (size_t)row * DIMD + cb + tx * 8;
        *(float4*)dst       = make_float4(v[0], v[1], v[2], v[3]);
        *(float4*)(dst + 4) = make_float4(v[4], v[5], v[6], v[7]);
    }
}

// ---------------- streaming attention stats: per row -> (p = 1/sumexp, argmax)
__global__ __launch_bounds__(256) void attn_kernel() {
    __shared__ float qs_[32][PITCH];
    __shared__ float ks_[32][PITCH];
    int tid = threadIdx.x, tx = tid & 15, ty = tid >> 4;
    int b = blockIdx.y;
    int rb = blockIdx.x * 128;

    const float* qbase  = g_q + ((size_t)b * NTOK + rb) * DIMD;
    const float* kbase0 = g_k + (size_t)b * NTOK * DIMD;

    float m[8], s[8];
    int ja[8];
#pragma unroll
    for (int r = 0; r < 8; r++) { m[r] = -CUDART_INF_F; s[r] = 0.f; ja[r] = 0; }

    for (int jt = 0; jt < NTOK / 128; jt++) {
        ull acc[8][4];
#pragma unroll
        for (int r = 0; r < 8; r++)
#pragma unroll
            for (int c = 0; c < 4; c++) acc[r][c] = 0ULL;

        const float* kbase = kbase0 + (size_t)jt * 128 * DIMD;
        for (int kk = 0; kk < DIMD; kk += 32) {
            load_tile_T(qs_, qbase + kk, tid);
            load_tile_T(ks_, kbase + kk, tid);
            __syncthreads();
#pragma unroll 8
            for (int k = 0; k < 32; k++) mma_step(qs_, ks_, k, tx, ty, acc);
            __syncthreads();
        }

        int colbase = jt * 128 + tx * 8;
#pragma unroll
        for (int r = 0; r < 8; r++) {
            float l[8];
#pragma unroll
            for (int c = 0; c < 4; c++) {
                float2 u = unpack2(acc[r][c]);
                l[2 * c]     = u.x * ATT_SCALE;
                l[2 * c + 1] = u.y * ATT_SCALE;
            }
            float tmax = l[0];
            int   targ = colbase;
#pragma unroll
            for (int c = 1; c < 8; c++)
                if (l[c] > tmax) { tmax = l[c]; targ = colbase + c; }
            // reduce (max, argmax) over the 16 lanes sharing this row
#pragma unroll
            for (int o = 1; o < 16; o <<= 1) {
                float om = __shfl_xor_sync(0xffffffffu, tmax, o);
                int   oa = __shfl_xor_sync(0xffffffffu, targ, o);
                if (om > tmax) { tmax = om; targ = oa; }
            }
            float nm = fmaxf(m[r], tmax);
            float tsum = 0.f;
#pragma unroll
            for (int c = 0; c < 8; c++) tsum += __expf(l[c] - nm);
#pragma unroll
            for (int o = 1; o < 16; o <<= 1)
                tsum += __shfl_xor_sync(0xffffffffu, tsum, o);
            s[r] = s[r] * __expf(m[r] - nm) + tsum;
            if (tmax > m[r]) ja[r] = targ;
            m[r] = nm;
        }
    }

    if (tx == 0) {
#pragma unroll
        for (int r = 0; r < 8; r++) {
            int row = b * NTOK + rb + ty * 8 + r;
            g_p[row] = 1.0f / s[r];   // p_max = exp(m - lse) = 1/sum
            g_j[row] = ja[r];
        }
    }
}

// ---------------- build Z: spike rows p * x[argmax], else 0 ------------------
__global__ __launch_bounds__(256) void zbuild_kernel(const float* __restrict__ x) {
    int row = blockIdx.x;
    int b = row >> 12;                 // NTOK = 4096
    float p = g_p[row];
    int tid = threadIdx.x;
    float v = 0.f;
    if (p >= THRESH) {
        const float* src = x + ((size_t)((b << 12) + g_j[row])) * DIMD;
        v = p * src[tid];
    }
    g_z[(size_t)row * DIMD + tid] = v;
}

// -----------------------------------------------------------------------------
extern "C" void kernel_launch(void* const* d_in, const int* in_sizes, int n_in,
                              void* d_out, int out_size) {
    (void)in_sizes; (void)n_in; (void)out_size;
    const float* x  = (const float*)d_in[0];
    const float* y  = (const float*)d_in[1];
    const float* Wq = (const float*)d_in[2];
    const float* Wk = (const float*)d_in[3];
    const float* Wv = (const float*)d_in[4];
    const float* Wp = (const float*)d_in[5];
    const float* bp = (const float*)d_in[6];
    float* out = (float*)d_out;

    float *q, *k, *z, *M;
    cudaGetSymbolAddress((void**)&q, g_q);
    cudaGetSymbolAddress((void**)&k, g_k);
    cudaGetSymbolAddress((void**)&z, g_z);
    cudaGetSymbolAddress((void**)&M, g_M);

    dim3 blk(256);
    // projections
    gemm_kernel<<<dim3(ROWS_TOTAL / 128, 2), blk>>>(x, Wq, q, nullptr, 0);
    gemm_kernel<<<dim3(ROWS_TOTAL / 128, 2), blk>>>(y, Wk, k, nullptr, 0);
    // fused projection matrix M = Wv @ Wp
    gemm_kernel<<<dim3(2, 2), blk>>>(Wv, Wp, M, nullptr, 0);
    // streaming softmax stats (max/argmax/sumexp) over q k^T
    attn_kernel<<<dim3(NTOK / 128, BATCH), blk>>>();
    // sparse spike rows
    zbuild_kernel<<<ROWS_TOTAL, blk>>>(x);
    // out = Z @ M + bp
    gemm_kernel<<<dim3(ROWS_TOTAL / 128, 2), blk>>>(z, M, out, bp, 1);
}

// round 2
// speedup vs baseline: 1.0015x; 1.0015x over previous
#include <cuda_runtime.h>
#include <math_constants.h>

#define DIMD 256
#define NTOK 4096
#define BATCH 4
#define ROWS_TOTAL (BATCH * NTOK)
#define ATT_SCALE 0.17677669529663687f
#define THRESH 0.6f
#define PITCH 132

typedef unsigned long long ull;

// ---------------- scratch (device globals; no allocation allowed) -------------
__device__ float g_q[ROWS_TOTAL * DIMD];
__device__ float g_k[ROWS_TOTAL * DIMD];
__device__ float g_z[ROWS_TOTAL * DIMD];
__device__ float g_M[DIMD * DIMD];
__device__ float g_p[ROWS_TOTAL];
__device__ int   g_j[ROWS_TOTAL];

// ---------------- f32x2 helpers ----------------------------------------------
__device__ __forceinline__ ull pack_dup(float x) {
    ull d;
    asm("mov.b64 %0, {%1, %1};" : "=l"(d) : "r"(__float_as_uint(x)));
    return d;
}
__device__ __forceinline__ void fma2(ull &d, ull a, ull b) {
    asm("fma.rn.f32x2 %0, %1, %2, %0;" : "+l"(d) : "l"(a), "l"(b));
}
__device__ __forceinline__ float2 unpack2(ull v) {
    unsigned lo, hi;
    asm("mov.b64 {%0, %1}, %2;" : "=r"(lo), "=r"(hi) : "l"(v));
    return make_float2(__uint_as_float(lo), __uint_as_float(hi));
}

// Load 128 rows x 32 k-cols chunk (row stride DIMD) TRANSPOSED into dst[32][PITCH]
// src must already point at (row_base*DIMD + kk).
__device__ __forceinline__ void load_tile_T(float (*dst)[PITCH], const float* __restrict__ src, int tid) {
#pragma unroll
    for (int l = 0; l < 4; l++) {
        int idx = tid + l * 256;
        int row = idx >> 3;
        int k4  = idx & 7;
        float4 v = *(const float4*)(src + row * DIMD + k4 * 4);
        dst[k4 * 4 + 0][row] = v.x;
        dst[k4 * 4 + 1][row] = v.y;
        dst[k4 * 4 + 2][row] = v.z;
        dst[k4 * 4 + 3][row] = v.w;
    }
}

// Load 32 k-rows x 128 cols chunk (row stride DIMD) NATURAL into dst[32][PITCH]
__device__ __forceinline__ void load_tile_N(float (*dst)[PITCH], const float* __restrict__ src, int tid) {
#pragma unroll
    for (int l = 0; l < 4; l++) {
        int idx = tid + l * 256;
        int k  = idx >> 5;
        int c4 = idx & 31;
        float4 v = *(const float4*)(src + k * DIMD + c4 * 4);
        *(float4*)&dst[k][c4 * 4] = v;   // row base = 528*k bytes, 16B aligned
    }
}

// one K-step of the 128x128 (8x8 per-thread) f32x2 micro-kernel
__device__ __forceinline__ void mma_step(const float (*as_)[PITCH], const float (*bs_)[PITCH],
                                         int k, int tx, int ty, ull acc[8][4]) {
    ull b[4];
    const ull* bp_ = (const ull*)&bs_[k][tx * 8];
#pragma unroll
    for (int c = 0; c < 4; c++) b[c] = bp_[c];

    const float2* ap_ = (const float2*)&as_[k][ty * 8];
    float2 a01 = ap_[0], a23 = ap_[1], a45 = ap_[2], a67 = ap_[3];
    ull A[8];
    A[0] = pack_dup(a01.x); A[1] = pack_dup(a01.y);
    A[2] = pack_dup(a23.x); A[3] = pack_dup(a23.y);
    A[4] = pack_dup(a45.x); A[5] = pack_dup(a45.y);
    A[6] = pack_dup(a67.x); A[7] = pack_dup(a67.y);
#pragma unroll
    for (int r = 0; r < 8; r++)
#pragma unroll
        for (int c = 0; c < 4; c++)
            fma2(acc[r][c], A[r], b[c]);
}

// ---------------- generic tiled GEMM: C[M x 256] = A[M x 256] @ B[256 x 256] (+bias)
__global__ __launch_bounds__(256) void gemm_kernel(const float* __restrict__ A,
                                                   const float* __restrict__ B,
                                                   float* __restrict__ C,
                                                   const float* __restrict__ bias,
                                                   int hasBias) {
    __shared__ float as_[32][PITCH];
    __shared__ float bs_[32][PITCH];
    int tid = threadIdx.x, tx = tid & 15, ty = tid >> 4;
    int rb = blockIdx.x * 128, cb = blockIdx.y * 128;

    ull acc[8][4];
#pragma unroll
    for (int r = 0; r < 8; r++)
#pragma unroll
        for (int c = 0; c < 4; c++) acc[r][c] = 0ULL;

    for (int kk = 0; kk < DIMD; kk += 32) {
        load_tile_T(as_, A + (size_t)rb * DIMD + kk, tid);
        load_tile_N(bs_, B + (size_t)kk * DIMD + cb, tid);
        __syncthreads();
#pragma unroll 8
        for (int k = 0; k < 32; k++) mma_step(as_, bs_, k, tx, ty, acc);
        __syncthreads();
    }

    float bv[8];
    if (hasBias) {
        float4 b0 = *(const float4*)(bias + cb + tx * 8);
        float4 b1 = *(const float4*)(bias + cb + tx * 8 + 4);
        bv[0] = b0.x; bv[1] = b0.y; bv[2] = b0.z; bv[3] = b0.w;
        bv[4] = b1.x; bv[5] = b1.y; bv[6] = b1.z; bv[7] = b1.w;
    } else {
#pragma unroll
        for (int i = 0; i < 8; i++) bv[i] = 0.f;
    }

#pragma unroll
    for (int r = 0; r < 8; r++) {
        float v[8];
#pragma unroll
        for (int c = 0; c < 4; c++) {
            float2 u = unpack2(acc[r][c]);
            v[2 * c]     = u.x + bv[2 * c];
            v[2 * c + 1] = u.y + bv[2 * c + 1];
        }
        int row = rb + ty * 8 + r;
        float* dst = C + (size_t)row * DIMD + cb + tx * 8;
        *(float4*)dst       = make_float4(v[0], v[1], v[2], v[3]);
        *(float4*)(dst + 4) = make_float4(v[4], v[5], v[6], v[7]);
    }
}

// ---------------- streaming attention stats: per row -> (p = 1/sumexp, argmax)
__global__ __launch_bounds__(256) void attn_kernel() {
    __shared__ float qs_[32][PITCH];
    __shared__ float ks_[32][PITCH];
    int tid = threadIdx.x, tx = tid & 15, ty = tid >> 4;
    int b = blockIdx.y;
    int rb = blockIdx.x * 128;

    const float* qbase  = g_q + ((size_t)b * NTOK + rb) * DIMD;
    const float* kbase0 = g_k + (size_t)b * NTOK * DIMD;

    float m[8], s[8];
    int ja[8];
#pragma unroll
    for (int r = 0; r < 8; r++) { m[r] = -CUDART_INF_F; s[r] = 0.f; ja[r] = 0; }

    for (int jt = 0; jt < NTOK / 128; jt++) {
        ull acc[8][4];
#pragma unroll
        for (int r = 0; r < 8; r++)
#pragma unroll
            for (int c = 0; c < 4; c++) acc[r][c] = 0ULL;

        const float* kbase = kbase0 + (size_t)jt * 128 * DIMD;
        for (int kk = 0; kk < DIMD; kk += 32) {
            load_tile_T(qs_, qbase + kk, tid);
            load_tile_T(ks_, kbase + kk, tid);
            __syncthreads();
#pragma unroll 8
            for (int k = 0; k < 32; k++) mma_step(qs_, ks_, k, tx, ty, acc);
            __syncthreads();
        }

        int colbase = jt * 128 + tx * 8;
#pragma unroll
        for (int r = 0; r < 8; r++) {
            float l[8];
#pragma unroll
            for (int c = 0; c < 4; c++) {
                float2 u = unpack2(acc[r][c]);
                l[2 * c]     = u.x * ATT_SCALE;
                l[2 * c + 1] = u.y * ATT_SCALE;
            }
            float tmax = l[0];
            int   targ = colbase;
#pragma unroll
            for (int c = 1; c < 8; c++)
                if (l[c] > tmax) { tmax = l[c]; targ = colbase + c; }
            // reduce (max, argmax) over the 16 lanes sharing this row
#pragma unroll
            for (int o = 1; o < 16; o <<= 1) {
                float om = __shfl_xor_sync(0xffffffffu, tmax, o);
                int   oa = __shfl_xor_sync(0xffffffffu, targ, o);
                if (om > tmax) { tmax = om; targ = oa; }
            }
            float nm = fmaxf(m[r], tmax);
            float tsum = 0.f;
#pragma unroll
            for (int c = 0; c < 8; c++) tsum += __expf(l[c] - nm);
#pragma unroll
            for (int o = 1; o < 16; o <<= 1)
                tsum += __shfl_xor_sync(0xffffffffu, tsum, o);
            s[r] = s[r] * __expf(m[r] - nm) + tsum;
            if (tmax > m[r]) ja[r] = targ;
            m[r] = nm;
        }
    }

    if (tx == 0) {
#pragma unroll
        for (int r = 0; r < 8; r++) {
            int row = b * NTOK + rb + ty * 8 + r;
            g_p[row] = 1.0f / s[r];   // p_max = exp(m - lse) = 1/sum
            g_j[row] = ja[r];
        }
    }
}

// ---------------- build Z: spike rows p * x[argmax], else 0 ------------------
__global__ __launch_bounds__(256) void zbuild_kernel(const float* __restrict__ x) {
    int row = blockIdx.x;
    int b = row >> 12;                 // NTOK = 4096
    float p = g_p[row];
    int tid = threadIdx.x;
    float v = 0.f;
    if (p >= THRESH) {
        const float* src = x + ((size_t)((b << 12) + g_j[row])) * DIMD;
        v = p * src[tid];
    }
    g_z[(size_t)row * DIMD + tid] = v;
}

// -----------------------------------------------------------------------------
extern "C" void kernel_launch(void* const* d_in, const int* in_sizes, int n_in,
                              void* d_out, int out_size) {
    (void)in_sizes; (void)n_in; (void)out_size;
    const float* x  = (const float*)d_in[0];
    const float* y  = (const float*)d_in[1];
    const float* Wq = (const float*)d_in[2];
    const float* Wk = (const float*)d_in[3];
    const float* Wv = (const float*)d_in[4];
    const float* Wp = (const float*)d_in[5];
    const float* bp = (const float*)d_in[6];
    float* out = (float*)d_out;

    float *q, *k, *z, *M;
    cudaGetSymbolAddress((void**)&q, g_q);
    cudaGetSymbolAddress((void**)&k, g_k);
    cudaGetSymbolAddress((void**)&z, g_z);
    cudaGetSymbolAddress((void**)&M, g_M);

    dim3 blk(256);
    // projections
    gemm_kernel<<<dim3(ROWS_TOTAL / 128, 2), blk>>>(x, Wq, q, nullptr, 0);
    gemm_kernel<<<dim3(ROWS_TOTAL / 128, 2), blk>>>(y, Wk, k, nullptr, 0);
    // fused projection matrix M = Wv @ Wp
    gemm_kernel<<<dim3(2, 2), blk>>>(Wv, Wp, M, nullptr, 0);
    // streaming softmax stats (max/argmax/sumexp) over q k^T
    attn_kernel<<<dim3(NTOK / 128, BATCH), blk>>>();
    // sparse spike rows
    zbuild_kernel<<<ROWS_TOTAL, blk>>>(x);
    // out = Z @ M + bp
    gemm_kernel<<<dim3(ROWS_TOTAL / 128, 2), blk>>>(z, M, out, bp, 1);
}